// round 1
// baseline (speedup 1.0000x reference)
#include <cuda_runtime.h>
#include <math.h>

#define NQb 12
#define SDIM 4096
#define NLayers 6
#define TPB 256

// Store amplitude k at smem slot phi(k): XORing bits 4-8 into bits 0-4 makes
// all three pass access patterns (local bits {8-11},{4-7},{0-3}) bank-conflict-free.
__device__ __forceinline__ int phi_idx(int k) { return k ^ ((k >> 4) & 31); }

// Composed CNOT-chain permutation: state_after[k] = state_before[sigma(k)].
// Chain = CNOT(0,1)..CNOT(10,11), CNOT(11,0); qubit i lives at bit (11-i).
__device__ __forceinline__ int sigma12(int x) {
    x ^= (x & 1) << 11;                 // CNOT(11,0): ctrl bit0, tgt bit11
#pragma unroll
    for (int p = 1; p <= 11; ++p)       // CNOT(i,i+1) for i=10..0
        x ^= ((x >> p) & 1) << (p - 1);
    return x;
}

// Apply 4 RY rotations on the 4 local bits of a 16-amplitude register group.
// local bit bb maps to qubit (qhi - bb). RY gate [[c,-s],[s,c]] acts on (a0,a1).
__device__ __forceinline__ void apply_ry4(float re[16], float im[16],
                                          const float* __restrict__ cryL,
                                          const float* __restrict__ sryL,
                                          int qhi) {
#pragma unroll
    for (int bb = 0; bb < 4; ++bb) {
        const float c = cryL[qhi - bb];
        const float s = sryL[qhi - bb];
        const int m = 1 << bb;
#pragma unroll
        for (int j0 = 0; j0 < 16; ++j0) {
            if (j0 & m) continue;       // compile-time pruned
            const int j1 = j0 | m;
            float a0 = re[j0], a1 = re[j1];
            re[j0] = c * a0 - s * a1;
            re[j1] = s * a0 + c * a1;
            a0 = im[j0]; a1 = im[j1];
            im[j0] = c * a0 - s * a1;
            im[j1] = s * a0 + c * a1;
        }
    }
}

__global__ void __launch_bounds__(TPB)
qsim_kernel(const float* __restrict__ xin, const float* __restrict__ params,
            const float* __restrict__ lin_w, const float* __restrict__ lin_b,
            float* __restrict__ out) {
    __shared__ float sre[SDIM];
    __shared__ float smi[SDIM];
    __shared__ float cenc[NQb], senc[NQb];
    __shared__ float cry[NLayers * NQb], sry[NLayers * NQb], tzp[NLayers * NQb];
    __shared__ int sigoff[16];
    __shared__ float red[TPB / 32];

    const int t = threadIdx.x;
    const int blk = blockIdx.x;

    // One-time precompute (accurate sin/cos; only 84 values).
    if (t < NQb) {
        float h = tanhf(xin[blk * NQb + t]) * 1.5707963267948966f; // tanh(x)*pi/2
        cenc[t] = cosf(h);
        senc[t] = sinf(h);
    }
    if (t < NLayers * NQb) {
        const int L = t / NQb, q = t - L * NQb;
        const float th = 0.5f * params[L * 2 * NQb + q];   // RY half-angle
        cry[t] = cosf(th);
        sry[t] = sinf(th);
        tzp[t] = params[L * 2 * NQb + NQb + q];            // RZ angle
    }
    if (t < 16) sigoff[t] = sigma12(t << 8);               // sigma is XOR-linear
    __syncthreads();

    const int sig_t = sigma12(t);
    float re[16], im[16];

    for (int L = 0; L < NLayers; ++L) {
        const float* cryL = cry + L * NQb;
        const float* sryL = sry + L * NQb;
        const float* tzL  = tzp + L * NQb;

        // ================= pass 0: local bits 8-11 (qubits 3..0) =================
        if (L == 0) {
            // Fused init: post-encoding product state, amplitude(k)=prod cos/sin.
            float base = 1.f;
#pragma unroll
            for (int p = 0; p < 8; ++p)
                base *= ((t >> p) & 1) ? senc[11 - p] : cenc[11 - p];
#pragma unroll
            for (int j = 0; j < 16; ++j) {
                float v = base;
#pragma unroll
                for (int bb = 0; bb < 4; ++bb)
                    v *= ((j >> bb) & 1) ? senc[3 - bb] : cenc[3 - bb];
                re[j] = v;
                im[j] = 0.f;
            }
        } else {
            // Fused CNOT-chain permutation of the previous layer (gather).
#pragma unroll
            for (int j = 0; j < 16; ++j) {
                const int a = phi_idx(sig_t ^ sigoff[j]);
                re[j] = sre[a];
                im[j] = smi[a];
            }
            __syncthreads();   // all permuted reads complete before overwrite
        }
        apply_ry4(re, im, cryL, sryL, 3);
#pragma unroll
        for (int j = 0; j < 16; ++j) {
            const int a = phi_idx(t | (j << 8));
            sre[a] = re[j];
            smi[a] = im[j];
        }
        __syncthreads();

        // ================= pass 1: local bits 4-7 (qubits 7..4) =================
        {
            const int kb = (t & 15) | ((t >> 4) << 8);
#pragma unroll
            for (int j = 0; j < 16; ++j) {
                const int a = phi_idx(kb | (j << 4));
                re[j] = sre[a];
                im[j] = smi[a];
            }
            apply_ry4(re, im, cryL, sryL, 7);
#pragma unroll
            for (int j = 0; j < 16; ++j) {
                const int a = phi_idx(kb | (j << 4));
                sre[a] = re[j];
                smi[a] = im[j];
            }
        }
        __syncthreads();

        // ======== pass 2: local bits 0-3 (qubits 11..8) + fused RZ(all 12) ========
        {
            const int kb = t << 4;
#pragma unroll
            for (int j = 0; j < 16; ++j) {
                const int a = phi_idx(kb | j);
                re[j] = sre[a];
                im[j] = smi[a];
            }
            apply_ry4(re, im, cryL, sryL, 11);

            // Fused RZ: phi(k) = sum_i t_i * (bit_i - 1/2)
            float T = 0.f;
#pragma unroll
            for (int q = 0; q < NQb; ++q) T += tzL[q];
            float phb = -0.5f * T;
#pragma unroll
            for (int p = 4; p < 12; ++p)
                if ((t >> (p - 4)) & 1) phb += tzL[11 - p];
#pragma unroll
            for (int j = 0; j < 16; ++j) {
                float ph = phb;
#pragma unroll
                for (int bb = 0; bb < 4; ++bb)
                    if ((j >> bb) & 1) ph += tzL[11 - bb];
                float cp, sp;
                __sincosf(ph, &sp, &cp);
                const float r = re[j], q_ = im[j];
                re[j] = r * cp - q_ * sp;
                im[j] = r * sp + q_ * cp;
            }
#pragma unroll
            for (int j = 0; j < 16; ++j) {
                const int a = phi_idx(kb | j);
                sre[a] = re[j];
                smi[a] = im[j];
            }
        }
        __syncthreads();
    }

    // Measurement: fold final CNOT permutation into the gather.
    // <sum_i Z_i> = sum_k |amp[k]|^2 * (12 - 2*popc(k))
    float acc = 0.f;
#pragma unroll
    for (int j = 0; j < 16; ++j) {
        const int k = t | (j << 8);
        const int a = phi_idx(sig_t ^ sigoff[j]);
        const float r = sre[a], q_ = smi[a];
        acc += (r * r + q_ * q_) * (float)(NQb - 2 * __popc(k));
    }
#pragma unroll
    for (int o = 16; o; o >>= 1) acc += __shfl_xor_sync(0xffffffffu, acc, o);
    if ((t & 31) == 0) red[t >> 5] = acc;
    __syncthreads();
    if (t == 0) {
        float m = 0.f;
#pragma unroll
        for (int w = 0; w < TPB / 32; ++w) m += red[w];
        const float z = (m / (float)NQb) * lin_w[0] + lin_b[0];
        out[blk] = 1.f / (1.f + expf(-z));
    }
}

extern "C" void kernel_launch(void* const* d_in, const int* in_sizes, int n_in,
                              void* d_out, int out_size) {
    const float* x      = (const float*)d_in[0];  // statistical_features (B,12)
    const float* params = (const float*)d_in[1];  // (144,)
    const float* lw     = (const float*)d_in[2];  // lin_w (1,1)
    const float* lb     = (const float*)d_in[3];  // lin_b (1,)
    const int Bn = in_sizes[0] / NQb;             // 512
    qsim_kernel<<<Bn, TPB>>>(x, params, lw, lb, (float*)d_out);
}